// round 11
// baseline (speedup 1.0000x reference)
#include <cuda_runtime.h>
#include <cstdint>

#define THREADS 512
#define NWARPS 16
#define RANK 8
#define K4 1024            // K/4
#define N4 1024            // N/4
#define MAXROWS 56
#define SLOTS 5            // x ring slots (16KB each) -> 80 KB
#define PRING 16           // partials ring rows
#define BLK 8              // rows per barrier block
#define LORA_SCALE 2.0f    // alpha/r = 16/8

// ---- packed f32x2 helpers (FFMA2 only reachable via PTX) ----
__device__ __forceinline__ uint64_t pack2(float lo, float hi) {
    uint64_t r; asm("mov.b64 %0, {%1, %2};" : "=l"(r) : "f"(lo), "f"(hi)); return r;
}
__device__ __forceinline__ void unpack2(uint64_t v, float& lo, float& hi) {
    asm("mov.b64 {%0, %1}, %2;" : "=f"(lo), "=f"(hi) : "l"(v));
}
__device__ __forceinline__ uint64_t fma2(uint64_t a, uint64_t b, uint64_t c) {
    uint64_t d; asm("fma.rn.f32x2 %0, %1, %2, %3;" : "=l"(d) : "l"(a), "l"(b), "l"(c)); return d;
}

// ---- cp.async (LDGSTS) helpers ----
__device__ __forceinline__ void cp_async16(uint32_t dst_smem, const void* src) {
    asm volatile("cp.async.cg.shared.global [%0], [%1], 16;"
                 :: "r"(dst_smem), "l"(src) : "memory");
}
__device__ __forceinline__ void cp_commit() {
    asm volatile("cp.async.commit_group;" ::: "memory");
}
template <int N>
__device__ __forceinline__ void cp_wait() {
    asm volatile("cp.async.wait_group %0;" :: "n"(N) : "memory");
}

// Phase 2 for two rows sharing the B smem loads.
__device__ __forceinline__ void phase2_rows(
    const float* __restrict__ s_t, const ulonglong2* __restrict__ sb2,
    float4* __restrict__ out4, int r0, int ra, int rbv, bool doB,
    int c0, int c1)
{
    const float4 tA0 = *reinterpret_cast<const float4*>(&s_t[ra * RANK]);
    const float4 tA1 = *reinterpret_cast<const float4*>(&s_t[ra * RANK + 4]);
    const float4 tB0 = *reinterpret_cast<const float4*>(&s_t[rbv * RANK]);
    const float4 tB1 = *reinterpret_cast<const float4*>(&s_t[rbv * RANK + 4]);
    const float tAv[8] = {tA0.x, tA0.y, tA0.z, tA0.w, tA1.x, tA1.y, tA1.z, tA1.w};
    const float tBv[8] = {tB0.x, tB0.y, tB0.z, tB0.w, tB1.x, tB1.y, tB1.z, tB1.w};

    uint64_t oA0 = 0, oA1 = 0, oA2 = 0, oA3 = 0;
    uint64_t oB0 = 0, oB1 = 0, oB2 = 0, oB3 = 0;
#pragma unroll
    for (int j = 0; j < RANK; j++) {
        ulonglong2 b0 = sb2[j * N4 + c0];   // LDS.128, conflict-free
        ulonglong2 b1 = sb2[j * N4 + c1];
        uint64_t ta = pack2(tAv[j], tAv[j]);
        uint64_t tb = pack2(tBv[j], tBv[j]);
        oA0 = fma2(ta, b0.x, oA0); oA1 = fma2(ta, b0.y, oA1);
        oA2 = fma2(ta, b1.x, oA2); oA3 = fma2(ta, b1.y, oA3);
        oB0 = fma2(tb, b0.x, oB0); oB1 = fma2(tb, b0.y, oB1);
        oB2 = fma2(tb, b1.x, oB2); oB3 = fma2(tb, b1.y, oB3);
    }
    float4 v0, v1;
    unpack2(oA0, v0.x, v0.y); unpack2(oA1, v0.z, v0.w);
    unpack2(oA2, v1.x, v1.y); unpack2(oA3, v1.z, v1.w);
    out4[(size_t)(r0 + ra) * N4 + c0] = v0;
    out4[(size_t)(r0 + ra) * N4 + c1] = v1;
    if (doB) {
        unpack2(oB0, v0.x, v0.y); unpack2(oB1, v0.z, v0.w);
        unpack2(oB2, v1.x, v1.y); unpack2(oB3, v1.z, v1.w);
        out4[(size_t)(r0 + rbv) * N4 + c0] = v0;
        out4[(size_t)(r0 + rbv) * N4 + c1] = v1;
    }
}

// Phase 2 for rows [base, base+n)
__device__ __forceinline__ void phase2_block(
    const float* __restrict__ s_t, const ulonglong2* __restrict__ sb2,
    float4* __restrict__ out4, int r0, int base, int n, int c0, int c1)
{
    for (int r = 0; r < n; r += 2) {
        const bool doB = (r + 1 < n);
        phase2_rows(s_t, sb2, out4, r0, base + r, doB ? base + r + 1 : base + r,
                    doB, c0, c1);
    }
}

__global__ __launch_bounds__(THREADS, 1)
void lora_fused_kernel(const float4* __restrict__ x4,
                       const float4* __restrict__ A4,
                       const float4* __restrict__ B4,
                       float4* __restrict__ out4,
                       int rows, int grid)
{
    extern __shared__ char raw[];
    float4* s_x    = reinterpret_cast<float4*>(raw);                       // [5][1024]   80 KB
    float4* s_b    = reinterpret_cast<float4*>(raw + SLOTS * K4 * 16);     // [8][1024]  128 KB
    float*  s_part = reinterpret_cast<float*>(raw + (SLOTS * K4 + RANK * N4) * 16); // [16][128] 8 KB
    float*  s_t    = s_part + PRING * 128;                                 // [56][8]   1.75 KB

    const int tid  = threadIdx.x;
    const int lane = tid & 31;
    const int warp = tid >> 5;

    const int r0 = (int)((long)blockIdx.x * rows / grid);
    const int r1 = (int)((long)(blockIdx.x + 1) * rows / grid);
    const int nr = r1 - r0;                    // 53 or 54

    const int c0 = tid;
    const int c1 = tid + THREADS;

    const uint32_t sx = (uint32_t)__cvta_generic_to_shared(s_x);
    const uint32_t sb = (uint32_t)__cvta_generic_to_shared(s_b);
    const uint32_t my_off = (uint32_t)tid * 16u;

    // ---------------- A cache: 2 chunks x 4 k x 4 j-pairs (64 regs) ----------
    uint64_t a2[2][4][4];
#pragma unroll
    for (int ch = 0; ch < 2; ch++) {
        const int c = ch ? c1 : c0;
#pragma unroll
        for (int kk = 0; kk < 4; kk++) {
            float4 lo = A4[c * 8 + kk * 2];
            float4 hi = A4[c * 8 + kk * 2 + 1];
            a2[ch][kk][0] = pack2(lo.x, lo.y);
            a2[ch][kk][1] = pack2(lo.z, lo.w);
            a2[ch][kk][2] = pack2(hi.x, hi.y);
            a2[ch][kk][3] = pack2(hi.z, hi.w);
        }
    }

    // ---------------- B -> smem via cp.async (group 0) ------------------------
#pragma unroll
    for (int i = 0; i < 16; i++) {
        const int idx = i * THREADS + tid;           // j*1024 + col linearized
        cp_async16(sb + (uint32_t)idx * 16u, B4 + idx);
    }
    cp_commit();

    // ---------------- Prologue: rows 0..4 into slots 0..4 ---------------------
#pragma unroll
    for (int d = 0; d < SLOTS; d++) {
        int row = (d < nr) ? d : (nr - 1);
        const size_t xb = (size_t)(r0 + row) * K4;
        uint32_t dst = sx + (uint32_t)d * (K4 * 16u) + my_off;
        cp_async16(dst,                 x4 + xb + c0);
        cp_async16(dst + THREADS * 16u, x4 + xb + c1);
        cp_commit();
    }

    const int j_mine = ((lane >> 4) & 1) * 4 + ((lane >> 3) & 1) * 2 + ((lane >> 2) & 1);
    const bool write_lane = (lane & 3) == 0;
    const bool h  = (lane & 16) != 0;
    const bool qb = (lane & 8) != 0;
    const bool ob = (lane & 4) != 0;

    const ulonglong2* sb2 = reinterpret_cast<const ulonglong2*>(s_b);

    // ================= Block pipeline: phase1(blk) | phase2(blk-8) ============
    for (int blk = 0; blk < nr; blk += BLK) {
        const int bend = (blk + BLK < nr) ? blk + BLK : nr;

        // ---- Phase 1 for rows blk..bend-1 (pairs) ----
        for (int r = blk; r < bend; r += 2) {
            cp_wait<3>();                  // B + rows r, r+1 complete

            const int slotA = r % SLOTS;
            const int slotB = (r + 1) % SLOTS;
            const float4 xa0 = s_x[slotA * K4 + c0];
            const float4 xa1 = s_x[slotA * K4 + c1];
            const float4 xb0 = s_x[slotB * K4 + c0];  // stale if r+1>=nr: discarded
            const float4 xb1 = s_x[slotB * K4 + c1];

            uint64_t pA2[4] = {0,0,0,0}, pB2[4] = {0,0,0,0};
            {
                const float fa[4] = {xa0.x, xa0.y, xa0.z, xa0.w};
                const float fb[4] = {xb0.x, xb0.y, xb0.z, xb0.w};
#pragma unroll
                for (int kk = 0; kk < 4; kk++) {
                    uint64_t sa  = pack2(fa[kk], fa[kk]);
                    uint64_t sbv = pack2(fb[kk], fb[kk]);
#pragma unroll
                    for (int jp = 0; jp < 4; jp++) {
                        pA2[jp] = fma2(sa,  a2[0][kk][jp], pA2[jp]);
                        pB2[jp] = fma2(sbv, a2[0][kk][jp], pB2[jp]);
                    }
                }
            }
            {
                const float fa[4] = {xa1.x, xa1.y, xa1.z, xa1.w};
                const float fb[4] = {xb1.x, xb1.y, xb1.z, xb1.w};
#pragma unroll
                for (int kk = 0; kk < 4; kk++) {
                    uint64_t sa  = pack2(fa[kk], fa[kk]);
                    uint64_t sbv = pack2(fb[kk], fb[kk]);
#pragma unroll
                    for (int jp = 0; jp < 4; jp++) {
                        pA2[jp] = fma2(sa,  a2[1][kk][jp], pA2[jp]);
                        pB2[jp] = fma2(sbv, a2[1][kk][jp], pB2[jp]);
                    }
                }
            }

            // Refill rows r+5, r+6 into just-freed slots; commit ALWAYS
            {
                const int rrA = r + 5;
                if (rrA < nr) {
                    const size_t xbs = (size_t)(r0 + rrA) * K4;
                    uint32_t dst = sx + (uint32_t)(rrA % SLOTS) * (K4 * 16u) + my_off;
                    cp_async16(dst,                 x4 + xbs + c0);
                    cp_async16(dst + THREADS * 16u, x4 + xbs + c1);
                }
                cp_commit();
                const int rrB = r + 6;
                if (rrB < nr) {
                    const size_t xbs = (size_t)(r0 + rrB) * K4;
                    uint32_t dst = sx + (uint32_t)(rrB % SLOTS) * (K4 * 16u) + my_off;
                    cp_async16(dst,                 x4 + xbs + c0);
                    cp_async16(dst + THREADS * 16u, x4 + xbs + c1);
                }
                cp_commit();
            }

            // Two interleaved folding butterflies
            float pA[8], pB[8];
#pragma unroll
            for (int jp = 0; jp < 4; jp++) {
                unpack2(pA2[jp], pA[2 * jp], pA[2 * jp + 1]);
                unpack2(pB2[jp], pB[2 * jp], pB[2 * jp + 1]);
            }
            float qA[4], qB[4];
#pragma unroll
            for (int m = 0; m < 4; m++) {
                float sendA = h ? pA[m] : pA[m + 4];
                float keepA = h ? pA[m + 4] : pA[m];
                float sendB = h ? pB[m] : pB[m + 4];
                float keepB = h ? pB[m + 4] : pB[m];
                qA[m] = keepA + __shfl_xor_sync(0xffffffffu, sendA, 16);
                qB[m] = keepB + __shfl_xor_sync(0xffffffffu, sendB, 16);
            }
            float uA[2], uB[2];
#pragma unroll
            for (int m = 0; m < 2; m++) {
                float sendA = qb ? qA[m] : qA[m + 2];
                float keepA = qb ? qA[m + 2] : qA[m];
                float sendB = qb ? qB[m] : qB[m + 2];
                float keepB = qb ? qB[m + 2] : qB[m];
                uA[m] = keepA + __shfl_xor_sync(0xffffffffu, sendA, 8);
                uB[m] = keepB + __shfl_xor_sync(0xffffffffu, sendB, 8);
            }
            float sendA = ob ? uA[0] : uA[1];
            float keepA = ob ? uA[1] : uA[0];
            float sendB = ob ? uB[0] : uB[1];
            float keepB = ob ? uB[1] : uB[0];
            float wA = keepA + __shfl_xor_sync(0xffffffffu, sendA, 4);
            float wB = keepB + __shfl_xor_sync(0xffffffffu, sendB, 4);
            wA += __shfl_xor_sync(0xffffffffu, wA, 2);
            wB += __shfl_xor_sync(0xffffffffu, wB, 2);
            wA += __shfl_xor_sync(0xffffffffu, wA, 1);
            wB += __shfl_xor_sync(0xffffffffu, wB, 1);

            // s_part ring: [row%16][j][w]
            if (write_lane) {
                s_part[(r & (PRING - 1)) * 128 + j_mine * 16 + warp] = wA;
                if (r + 1 < nr)
                    s_part[((r + 1) & (PRING - 1)) * 128 + j_mine * 16 + warp] = wB;
            }
        }

        __syncthreads();   // s_part(blk..bend-1) visible; s_t(prev block) visible

        // ---- Reducers: threads 0-63 fold partials for fresh rows -------------
        if (tid < 64) {
            const int row = blk + (tid >> 3);
            if (row < bend) {
                const int j = tid & 7;
                const float4* p4 = reinterpret_cast<const float4*>(
                    &s_part[(row & (PRING - 1)) * 128 + j * 16]);
                float4 v0 = p4[0], v1 = p4[1], v2 = p4[2], v3 = p4[3];
                float s = ((v0.x + v0.y) + (v0.z + v0.w))
                        + ((v1.x + v1.y) + (v1.z + v1.w))
                        + ((v2.x + v2.y) + (v2.z + v2.w))
                        + ((v3.x + v3.y) + (v3.z + v3.w));
                s_t[row * RANK + j] = LORA_SCALE * s;
            }
        }

        // ---- Phase 2 for the PREVIOUS block (writes overlap next block's reads)
        if (blk >= BLK)
            phase2_block(s_t, sb2, out4, r0, blk - BLK, BLK, c0, c1);
    }

    // ---------------- Epilogue: last block ------------------------------------
    __syncthreads();       // s_t(last block) visible
    const int lb = ((nr - 1) / BLK) * BLK;
    phase2_block(s_t, sb2, out4, r0, lb, nr - lb, c0, c1);
}

extern "C" void kernel_launch(void* const* d_in, const int* in_sizes, int n_in,
                              void* d_out, int out_size)
{
    const float4* x4 = (const float4*)d_in[0];   // [4,2048,4096]
    const float4* A4 = (const float4*)d_in[1];   // [4096,8]
    const float4* B4 = (const float4*)d_in[2];   // [8,4096]
    float4* out4 = (float4*)d_out;

    const int K    = in_sizes[1] / RANK;         // 4096
    const int rows = in_sizes[0] / K;            // 8192

    int sms = 148;
    cudaDeviceGetAttribute(&sms, cudaDevAttrMultiProcessorCount, 0);

    const int smem = SLOTS * K4 * 16 +                    // x ring:    81920
                     RANK * N4 * 16 +                     // B tile:   131072
                     PRING * 128 * (int)sizeof(float) +   // partials:   8192
                     MAXROWS * RANK * (int)sizeof(float); // t:          1792
    cudaFuncSetAttribute(lora_fused_kernel,
                         cudaFuncAttributeMaxDynamicSharedMemorySize, smem);

    lora_fused_kernel<<<sms, THREADS, smem>>>(x4, A4, B4, out4, rows, sms);
}

// round 12
// speedup vs baseline: 1.5015x; 1.5015x over previous
#include <cuda_runtime.h>
#include <cstdint>

#define THREADS 512
#define NWARPS 16
#define RANK 8
#define K4 1024            // K/4
#define N4 1024            // N/4
#define MAXROWS 64
#define SLOTS 8            // x ring slots (16KB each)
#define SBUFS 4            // staging buffers per warp (1KB each)
#define LORA_SCALE 2.0f    // alpha/r = 16/8

// ---- packed f32x2 helpers (FFMA2 only reachable via PTX) ----
__device__ __forceinline__ uint64_t pack2(float lo, float hi) {
    uint64_t r; asm("mov.b64 %0, {%1, %2};" : "=l"(r) : "f"(lo), "f"(hi)); return r;
}
__device__ __forceinline__ void unpack2(uint64_t v, float& lo, float& hi) {
    asm("mov.b64 {%0, %1}, %2;" : "=f"(lo), "=f"(hi) : "l"(v));
}
__device__ __forceinline__ uint64_t fma2(uint64_t a, uint64_t b, uint64_t c) {
    uint64_t d; asm("fma.rn.f32x2 %0, %1, %2, %3;" : "=l"(d) : "l"(a), "l"(b), "l"(c)); return d;
}

// ---- cp.async (LDGSTS) helpers ----
__device__ __forceinline__ void cp_async16(uint32_t dst_smem, const void* src) {
    asm volatile("cp.async.cg.shared.global [%0], [%1], 16;"
                 :: "r"(dst_smem), "l"(src) : "memory");
}
__device__ __forceinline__ void cp_commit() {
    asm volatile("cp.async.commit_group;" ::: "memory");
}
template <int N>
__device__ __forceinline__ void cp_wait() {
    asm volatile("cp.async.wait_group %0;" :: "n"(N) : "memory");
}

// ---- TMA 1D bulk store (smem -> gmem), bulk_group based ----
__device__ __forceinline__ void bulk_store(void* gdst, uint32_t ssrc, uint32_t bytes) {
    asm volatile("cp.async.bulk.global.shared::cta.bulk_group [%0], [%1], %2;"
                 :: "l"(gdst), "r"(ssrc), "r"(bytes) : "memory");
}
__device__ __forceinline__ void bulk_commit() {
    asm volatile("cp.async.bulk.commit_group;" ::: "memory");
}
template <int N>
__device__ __forceinline__ void bulk_wait_read() {   // source buffer reusable
    asm volatile("cp.async.bulk.wait_group.read %0;" :: "n"(N) : "memory");
}
__device__ __forceinline__ void bulk_wait_all() {
    asm volatile("cp.async.bulk.wait_group 0;" ::: "memory");
}
__device__ __forceinline__ void fence_async_proxy() {
    asm volatile("fence.proxy.async.shared::cta;" ::: "memory");
}

__global__ __launch_bounds__(THREADS, 1)
void lora_fused_kernel(const float4* __restrict__ x4,
                       const float4* __restrict__ A4,
                       const float4* __restrict__ B4,
                       float4* __restrict__ out4,
                       int rows, int grid)
{
    extern __shared__ char raw[];
    float4* s_x    = reinterpret_cast<float4*>(raw);                  // [8][1024]  128 KB
    float*  s_part = reinterpret_cast<float*>(raw + SLOTS * K4 * 16); // [64][16][8] 32 KB
    float*  s_t    = s_part + MAXROWS * NWARPS * 8;                   // [64][8]   2 KB
    float4* s_stg  = reinterpret_cast<float4*>(
        raw + SLOTS * K4 * 16 + (MAXROWS * NWARPS * 8 + MAXROWS * RANK) * 4); // [4][16][64] 64 KB

    const int tid  = threadIdx.x;
    const int lane = tid & 31;
    const int warp = tid >> 5;

    const int r0 = (int)((long)blockIdx.x * rows / grid);
    const int r1 = (int)((long)(blockIdx.x + 1) * rows / grid);
    const int nr = r1 - r0;                    // ~53-54

    const int c0 = tid;
    const int c1 = tid + THREADS;

    const uint32_t sx = (uint32_t)__cvta_generic_to_shared(s_x);
    const uint32_t my_off = (uint32_t)tid * 16u;

    // ---------------- A cache: 2 chunks x 4 k x 4 j-pairs (64 regs) ----------
    uint64_t a2[2][4][4];
#pragma unroll
    for (int ch = 0; ch < 2; ch++) {
        const int c = ch ? c1 : c0;
#pragma unroll
        for (int kk = 0; kk < 4; kk++) {
            float4 lo = A4[c * 8 + kk * 2];
            float4 hi = A4[c * 8 + kk * 2 + 1];
            a2[ch][kk][0] = pack2(lo.x, lo.y);
            a2[ch][kk][1] = pack2(lo.z, lo.w);
            a2[ch][kk][2] = pack2(hi.x, hi.y);
            a2[ch][kk][3] = pack2(hi.z, hi.w);
        }
    }

    const int j_mine = ((lane >> 4) & 1) * 4 + ((lane >> 3) & 1) * 2 + ((lane >> 2) & 1);
    const bool write_lane = (lane & 3) == 0;
    const bool h  = (lane & 16) != 0;
    const bool qb = (lane & 8) != 0;
    const bool ob = (lane & 4) != 0;

    // ---------------- Prologue: stage rows 0..5 into the ring ----------------
#pragma unroll
    for (int d = 0; d < 6; d++) {
        int row = (d < nr) ? d : (nr - 1);
        const size_t xb = (size_t)(r0 + row) * K4;
        uint32_t dst = sx + (uint32_t)(d & (SLOTS - 1)) * (K4 * 16u) + my_off;
        cp_async16(dst,                 x4 + xb + c0);
        cp_async16(dst + THREADS * 16u, x4 + xb + c1);
        cp_commit();
    }

    // ---------------- Phase 1: 2 rows/iter (proven R6 structure) --------------
    for (int rb = 0; rb < nr; rb += 2) {
        cp_wait<4>();                      // rows rb, rb+1 complete

        const int sA = rb & (SLOTS - 1);
        const int sB = (rb + 1) & (SLOTS - 1);
        const float4 xa0 = s_x[sA * K4 + c0];
        const float4 xa1 = s_x[sA * K4 + c1];
        const float4 xb0 = s_x[sB * K4 + c0];  // stale if rb+1>=nr: discarded
        const float4 xb1 = s_x[sB * K4 + c1];

        uint64_t pA2[4] = {0,0,0,0}, pB2[4] = {0,0,0,0};
        {
            const float fa[4] = {xa0.x, xa0.y, xa0.z, xa0.w};
            const float fb[4] = {xb0.x, xb0.y, xb0.z, xb0.w};
#pragma unroll
            for (int kk = 0; kk < 4; kk++) {
                uint64_t sa  = pack2(fa[kk], fa[kk]);
                uint64_t sbv = pack2(fb[kk], fb[kk]);
#pragma unroll
                for (int jp = 0; jp < 4; jp++) {
                    pA2[jp] = fma2(sa,  a2[0][kk][jp], pA2[jp]);
                    pB2[jp] = fma2(sbv, a2[0][kk][jp], pB2[jp]);
                }
            }
        }
        {
            const float fa[4] = {xa1.x, xa1.y, xa1.z, xa1.w};
            const float fb[4] = {xb1.x, xb1.y, xb1.z, xb1.w};
#pragma unroll
            for (int kk = 0; kk < 4; kk++) {
                uint64_t sa  = pack2(fa[kk], fa[kk]);
                uint64_t sbv = pack2(fb[kk], fb[kk]);
#pragma unroll
                for (int jp = 0; jp < 4; jp++) {
                    pA2[jp] = fma2(sa,  a2[1][kk][jp], pA2[jp]);
                    pB2[jp] = fma2(sbv, a2[1][kk][jp], pB2[jp]);
                }
            }
        }

        // Refill rows rb+6, rb+7; commit ALWAYS (empty groups keep invariant)
        {
            const int rrA = rb + 6;
            if (rrA < nr) {
                const size_t xbs = (size_t)(r0 + rrA) * K4;
                uint32_t dst = sx + (uint32_t)(rrA & (SLOTS - 1)) * (K4 * 16u) + my_off;
                cp_async16(dst,                 x4 + xbs + c0);
                cp_async16(dst + THREADS * 16u, x4 + xbs + c1);
            }
            cp_commit();
            const int rrB = rb + 7;
            if (rrB < nr) {
                const size_t xbs = (size_t)(r0 + rrB) * K4;
                uint32_t dst = sx + (uint32_t)(rrB & (SLOTS - 1)) * (K4 * 16u) + my_off;
                cp_async16(dst,                 x4 + xbs + c0);
                cp_async16(dst + THREADS * 16u, x4 + xbs + c1);
            }
            cp_commit();
        }

        // Two interleaved folding butterflies
        float pA[8], pB[8];
#pragma unroll
        for (int jp = 0; jp < 4; jp++) {
            unpack2(pA2[jp], pA[2 * jp], pA[2 * jp + 1]);
            unpack2(pB2[jp], pB[2 * jp], pB[2 * jp + 1]);
        }
        float qA[4], qB[4];
#pragma unroll
        for (int m = 0; m < 4; m++) {
            float sendA = h ? pA[m] : pA[m + 4];
            float keepA = h ? pA[m + 4] : pA[m];
            float sendB = h ? pB[m] : pB[m + 4];
            float keepB = h ? pB[m + 4] : pB[m];
            qA[m] = keepA + __shfl_xor_sync(0xffffffffu, sendA, 16);
            qB[m] = keepB + __shfl_xor_sync(0xffffffffu, sendB, 16);
        }
        float uA[2], uB[2];
#pragma unroll
        for (int m = 0; m < 2; m++) {
            float sendA = qb ? qA[m] : qA[m + 2];
            float keepA = qb ? qA[m + 2] : qA[m];
            float sendB = qb ? qB[m] : qB[m + 2];
            float keepB = qb ? qB[m + 2] : qB[m];
            uA[m] = keepA + __shfl_xor_sync(0xffffffffu, sendA, 8);
            uB[m] = keepB + __shfl_xor_sync(0xffffffffu, sendB, 8);
        }
        float sendA = ob ? uA[0] : uA[1];
        float keepA = ob ? uA[1] : uA[0];
        float sendB = ob ? uB[0] : uB[1];
        float keepB = ob ? uB[1] : uB[0];
        float wA = keepA + __shfl_xor_sync(0xffffffffu, sendA, 4);
        float wB = keepB + __shfl_xor_sync(0xffffffffu, sendB, 4);
        wA += __shfl_xor_sync(0xffffffffu, wA, 2);
        wB += __shfl_xor_sync(0xffffffffu, wB, 2);
        wA += __shfl_xor_sync(0xffffffffu, wA, 1);
        wB += __shfl_xor_sync(0xffffffffu, wB, 1);

        if (write_lane) {
            s_part[rb * (NWARPS * 8) + warp * 8 + j_mine] = wA;
            if (rb + 1 < nr)
                s_part[(rb + 1) * (NWARPS * 8) + warp * 8 + j_mine] = wB;
        }
    }

    // ---------------- B cache: warp-contiguous columns, pre-scaled ------------
    // Thread handles output float4 columns  warp*64+lane  and  warp*64+32+lane.
    const int col0 = warp * 64 + lane;
    const int col1 = col0 + 32;
    uint64_t b2[8][4];
#pragma unroll
    for (int j = 0; j < RANK; j++) {
        float4 v0 = B4[j * N4 + col0];
        float4 v1 = B4[j * N4 + col1];
        v0.x *= LORA_SCALE; v0.y *= LORA_SCALE; v0.z *= LORA_SCALE; v0.w *= LORA_SCALE;
        v1.x *= LORA_SCALE; v1.y *= LORA_SCALE; v1.z *= LORA_SCALE; v1.w *= LORA_SCALE;
        b2[j][0] = pack2(v0.x, v0.y); b2[j][1] = pack2(v0.z, v0.w);
        b2[j][2] = pack2(v1.x, v1.y); b2[j][3] = pack2(v1.z, v1.w);
    }

    __syncthreads();

    // ---------------- Cross-warp reduce into s_t ------------------------------
    for (int i = tid; i < nr * RANK; i += THREADS) {
        const int row = i >> 3, j = i & 7;
        float s = 0.0f;
#pragma unroll
        for (int w = 0; w < NWARPS; w++)
            s += s_part[row * (NWARPS * 8) + w * 8 + j];
        s_t[i] = s;
    }
    __syncthreads();

    // ---------------- Phase 2: compute -> STS staging -> TMA bulk store -------
    // Per warp: 1 KB contiguous slice of each row; 4-deep staging ring.
    const uint32_t stg_base = (uint32_t)__cvta_generic_to_shared(s_stg);
    float* o_raw = reinterpret_cast<float*>(out4);

    for (int r = 0; r < nr; r++) {
        const int buf = r & (SBUFS - 1);

        if (r >= SBUFS) {                  // buffer reusable once its store's read is done
            if (lane == 0) bulk_wait_read<SBUFS - 1>();
            __syncwarp();
        }

        const float4 t0 = *reinterpret_cast<const float4*>(&s_t[r * RANK]);
        const float4 t1 = *reinterpret_cast<const float4*>(&s_t[r * RANK + 4]);
        const float tv[8] = {t0.x, t0.y, t0.z, t0.w, t1.x, t1.y, t1.z, t1.w};

        uint64_t o0 = 0, o1 = 0, o2 = 0, o3 = 0;
#pragma unroll
        for (int j = 0; j < RANK; j++) {
            uint64_t ts = pack2(tv[j], tv[j]);
            o0 = fma2(ts, b2[j][0], o0);
            o1 = fma2(ts, b2[j][1], o1);
            o2 = fma2(ts, b2[j][2], o2);
            o3 = fma2(ts, b2[j][3], o3);
        }
        float4 va, vb;
        unpack2(o0, va.x, va.y); unpack2(o1, va.z, va.w);
        unpack2(o2, vb.x, vb.y); unpack2(o3, vb.z, vb.w);

        // STS.128 into this warp's staging buffer (conflict-free)
        float4* wbuf = s_stg + (buf * NWARPS + warp) * 64;
        wbuf[lane]      = va;
        wbuf[lane + 32] = vb;

        __syncwarp();                      // STS visible to lane 0's fence
        if (lane == 0) {
            fence_async_proxy();
            void* gdst = o_raw + ((size_t)(r0 + r) * N4 + (size_t)warp * 64) * 4;
            bulk_store(gdst, stg_base + (uint32_t)(buf * NWARPS + warp) * 1024u, 1024u);
            bulk_commit();
        }
    }

    if (lane == 0) bulk_wait_all();        // all writes posted before exit
}

extern "C" void kernel_launch(void* const* d_in, const int* in_sizes, int n_in,
                              void* d_out, int out_size)
{
    const float4* x4 = (const float4*)d_in[0];   // [4,2048,4096]
    const float4* A4 = (const float4*)d_in[1];   // [4096,8]
    const float4* B4 = (const float4*)d_in[2];   // [8,4096]
    float4* out4 = (float4*)d_out;

    const int K    = in_sizes[1] / RANK;         // 4096
    const int rows = in_sizes[0] / K;            // 8192

    int sms = 148;
    cudaDeviceGetAttribute(&sms, cudaDevAttrMultiProcessorCount, 0);

    const int smem = SLOTS * K4 * 16 +                           // x ring:   131072
                     MAXROWS * NWARPS * 8 * (int)sizeof(float) + // partials:  32768
                     MAXROWS * RANK * (int)sizeof(float) +       // t:          2048
                     SBUFS * NWARPS * 64 * 16;                   // staging:   65536
    cudaFuncSetAttribute(lora_fused_kernel,
                         cudaFuncAttributeMaxDynamicSharedMemorySize, smem);

    lora_fused_kernel<<<sms, THREADS, smem>>>(x4, A4, B4, out4, rows, sms);
}

// round 13
// speedup vs baseline: 1.5327x; 1.0208x over previous
#include <cuda_runtime.h>
#include <cstdint>

#define THREADS 512
#define NWARPS 16
#define RANK 8
#define K4 1024            // K/4
#define N4 1024            // N/4
#define MAXROWS 64
#define PSLOTS 4           // pair slots (2 rows = 32 KB each)
#define LORA_SCALE 2.0f    // alpha/r = 16/8

// ---- packed f32x2 helpers (FFMA2 only reachable via PTX) ----
__device__ __forceinline__ uint64_t pack2(float lo, float hi) {
    uint64_t r; asm("mov.b64 %0, {%1, %2};" : "=l"(r) : "f"(lo), "f"(hi)); return r;
}
__device__ __forceinline__ void unpack2(uint64_t v, float& lo, float& hi) {
    asm("mov.b64 {%0, %1}, %2;" : "=f"(lo), "=f"(hi) : "l"(v));
}
__device__ __forceinline__ uint64_t fma2(uint64_t a, uint64_t b, uint64_t c) {
    uint64_t d; asm("fma.rn.f32x2 %0, %1, %2, %3;" : "=l"(d) : "l"(a), "l"(b), "l"(c)); return d;
}

// ---- mbarrier + TMA 1D bulk load helpers ----
__device__ __forceinline__ void mbar_init(uint32_t mbar, uint32_t cnt) {
    asm volatile("mbarrier.init.shared.b64 [%0], %1;" :: "r"(mbar), "r"(cnt) : "memory");
}
__device__ __forceinline__ void mbar_expect_tx(uint32_t mbar, uint32_t bytes) {
    asm volatile("mbarrier.arrive.expect_tx.shared.b64 _, [%0], %1;"
                 :: "r"(mbar), "r"(bytes) : "memory");
}
__device__ __forceinline__ void mbar_arrive(uint32_t mbar) {
    asm volatile("mbarrier.arrive.shared.b64 _, [%0];" :: "r"(mbar) : "memory");
}
__device__ __forceinline__ void mbar_wait(uint32_t mbar, uint32_t parity) {
    asm volatile(
        "{\n\t"
        ".reg .pred P1;\n\t"
        "WAIT_%=:\n\t"
        "mbarrier.try_wait.parity.acquire.cta.shared::cta.b64 P1, [%0], %1, 0x989680;\n\t"
        "@P1 bra.uni DONE_%=;\n\t"
        "bra.uni WAIT_%=;\n\t"
        "DONE_%=:\n\t"
        "}"
        :: "r"(mbar), "r"(parity) : "memory");
}
__device__ __forceinline__ void tma_load_1d(uint32_t dst_smem, const void* src,
                                            uint32_t bytes, uint32_t mbar) {
    asm volatile("cp.async.bulk.shared::cta.global.mbarrier::complete_tx::bytes "
                 "[%0], [%1], %2, [%3];"
                 :: "r"(dst_smem), "l"(src), "r"(bytes), "r"(mbar) : "memory");
}

__global__ __launch_bounds__(THREADS, 1)
void lora_fused_kernel(const float4* __restrict__ x4,
                       const float4* __restrict__ A4,
                       const float4* __restrict__ B4,
                       float4* __restrict__ out4,
                       int rows, int grid)
{
    extern __shared__ char raw[];
    float4* s_x    = reinterpret_cast<float4*>(raw);                    // [4][2048]  128 KB
    float*  s_part = reinterpret_cast<float*>(raw + PSLOTS * 2048 * 16);// [64][16][8] 32 KB
    float*  s_t    = s_part + MAXROWS * NWARPS * 8;                     // [64][8]     2 KB
    uint64_t* s_mb = reinterpret_cast<uint64_t*>(s_t + MAXROWS * RANK); // [4][2]     64 B

    const int tid  = threadIdx.x;
    const int lane = tid & 31;
    const int warp = tid >> 5;

    const int r0 = (int)((long)blockIdx.x * rows / grid);
    const int r1 = (int)((long)(blockIdx.x + 1) * rows / grid);
    const int nr = r1 - r0;                    // 53 or 54
    const int npairs = (nr + 1) >> 1;          // 27

    const int c0 = tid;
    const int c1 = tid + THREADS;

    const uint32_t sx = (uint32_t)__cvta_generic_to_shared(s_x);
    const uint32_t mb = (uint32_t)__cvta_generic_to_shared(s_mb);
    // full[s] = mb + s*16 ; empty[s] = mb + s*16 + 8

    // ---------------- A cache: 2 chunks x 4 k x 4 j-pairs (64 regs) ----------
    uint64_t a2[2][4][4];
#pragma unroll
    for (int ch = 0; ch < 2; ch++) {
        const int c = ch ? c1 : c0;
#pragma unroll
        for (int kk = 0; kk < 4; kk++) {
            float4 lo = A4[c * 8 + kk * 2];
            float4 hi = A4[c * 8 + kk * 2 + 1];
            a2[ch][kk][0] = pack2(lo.x, lo.y);
            a2[ch][kk][1] = pack2(lo.z, lo.w);
            a2[ch][kk][2] = pack2(hi.x, hi.y);
            a2[ch][kk][3] = pack2(hi.z, hi.w);
        }
    }

    // ---------------- mbarrier init + prologue: 3 pairs in flight ------------
    if (tid == 0) {
#pragma unroll
        for (int s = 0; s < PSLOTS; s++) {
            mbar_init(mb + s * 16, 1);        // full: expect_tx based
            mbar_init(mb + s * 16 + 8, 16);   // empty: one arrive per warp
        }
    }
    __syncthreads();

    if (tid == 0) {
#pragma unroll
        for (int p = 0; p < 3; p++) {
            const uint32_t bytes = (2 * p + 1 < nr) ? 32768u : 16384u;
            mbar_expect_tx(mb + p * 16, bytes);
            tma_load_1d(sx + (uint32_t)p * 32768u, x4 + (size_t)(r0 + 2 * p) * K4,
                        bytes, mb + p * 16);
        }
    }

    const int j_mine = ((lane >> 4) & 1) * 4 + ((lane >> 3) & 1) * 2 + ((lane >> 2) & 1);
    const bool write_lane = (lane & 3) == 0;
    const bool h  = (lane & 16) != 0;
    const bool qb = (lane & 8) != 0;
    const bool ob = (lane & 4) != 0;

    // ---------------- Phase 1: one pair (2 rows) per iteration ---------------
    for (int pb = 0; pb < npairs; pb++) {
        const int rb   = pb * 2;
        const int slot = pb & (PSLOTS - 1);

        mbar_wait(mb + slot * 16, (uint32_t)((pb >> 2) & 1));   // full

        const float4* sp = s_x + slot * 2048;
        const float4 xa0 = sp[c0];
        const float4 xa1 = sp[c1];
        const float4 xb0 = sp[1024 + c0];   // garbage if rb+1>=nr: discarded
        const float4 xb1 = sp[1024 + c1];

        // Producer: issue pair pb+3 (overlaps this iteration's compute)
        if (tid == 0) {
            const int tp = pb + 3;
            if (tp < npairs) {
                const int ts = tp & (PSLOTS - 1);
                const int k  = tp >> 2;
                if (k >= 1)
                    mbar_wait(mb + ts * 16 + 8, (uint32_t)((k - 1) & 1));  // empty
                const uint32_t bytes = (2 * tp + 1 < nr) ? 32768u : 16384u;
                mbar_expect_tx(mb + ts * 16, bytes);
                tma_load_1d(sx + (uint32_t)ts * 32768u,
                            x4 + (size_t)(r0 + 2 * tp) * K4, bytes, mb + ts * 16);
            }
        }

        uint64_t pA2[4] = {0,0,0,0}, pB2[4] = {0,0,0,0};
        {
            const float fa[4] = {xa0.x, xa0.y, xa0.z, xa0.w};
            const float fb[4] = {xb0.x, xb0.y, xb0.z, xb0.w};
#pragma unroll
            for (int kk = 0; kk < 4; kk++) {
                uint64_t sa  = pack2(fa[kk], fa[kk]);
                uint64_t sbv = pack2(fb[kk], fb[kk]);
#pragma unroll
                for (int jp = 0; jp < 4; jp++) {
                    pA2[jp] = fma2(sa,  a2[0][kk][jp], pA2[jp]);
                    pB2[jp] = fma2(sbv, a2[0][kk][jp], pB2[jp]);
                }
            }
        }
        {
            const float fa[4] = {xa1.x, xa1.y, xa1.z, xa1.w};
            const float fb[4] = {xb1.x, xb1.y, xb1.z, xb1.w};
#pragma unroll
            for (int kk = 0; kk < 4; kk++) {
                uint64_t sa  = pack2(fa[kk], fa[kk]);
                uint64_t sbv = pack2(fb[kk], fb[kk]);
#pragma unroll
                for (int jp = 0; jp < 4; jp++) {
                    pA2[jp] = fma2(sa,  a2[1][kk][jp], pA2[jp]);
                    pB2[jp] = fma2(sbv, a2[1][kk][jp], pB2[jp]);
                }
            }
        }

        // Two interleaved folding butterflies
        float pA[8], pB[8];
#pragma unroll
        for (int jp = 0; jp < 4; jp++) {
            unpack2(pA2[jp], pA[2 * jp], pA[2 * jp + 1]);
            unpack2(pB2[jp], pB[2 * jp], pB[2 * jp + 1]);
        }
        float qA[4], qB[4];
#pragma unroll
        for (int m = 0; m < 4; m++) {
            float sendA = h ? pA[m] : pA[m + 4];
            float keepA = h ? pA[m + 4] : pA[m];
            float sendB = h ? pB[m] : pB[m + 4];
            float keepB = h ? pB[m + 4] : pB[m];
            qA[m] = keepA + __shfl_xor_sync(0xffffffffu, sendA, 16);
            qB[m] = keepB + __shfl_xor_sync(0xffffffffu, sendB, 16);
        }
        float uA[2], uB[2];
#pragma unroll
        for (int m = 0; m < 2; m++) {
            float sendA = qb ? qA[m] : qA[m + 2];
            float keepA = qb ? qA[m + 2] : qA[m];
            float sendB = qb ? qB[m] : qB[m + 2];
            float keepB = qb ? qB[m + 2] : qB[m];
            uA[m] = keepA + __shfl_xor_sync(0xffffffffu, sendA, 8);
            uB[m] = keepB + __shfl_xor_sync(0xffffffffu, sendB, 8);
        }
        float sendA = ob ? uA[0] : uA[1];
        float keepA = ob ? uA[1] : uA[0];
        float sendB = ob ? uB[0] : uB[1];
        float keepB = ob ? uB[1] : uB[0];
        float wA = keepA + __shfl_xor_sync(0xffffffffu, sendA, 4);
        float wB = keepB + __shfl_xor_sync(0xffffffffu, sendB, 4);
        wA += __shfl_xor_sync(0xffffffffu, wA, 2);
        wB += __shfl_xor_sync(0xffffffffu, wB, 2);
        wA += __shfl_xor_sync(0xffffffffu, wA, 1);
        wB += __shfl_xor_sync(0xffffffffu, wB, 1);

        if (write_lane) {
            s_part[rb * (NWARPS * 8) + warp * 8 + j_mine] = wA;
            if (rb + 1 < nr)
                s_part[(rb + 1) * (NWARPS * 8) + warp * 8 + j_mine] = wB;
        }

        __syncwarp();                       // whole warp done reading the slot
        if (lane == 0)
            mbar_arrive(mb + slot * 16 + 8);   // empty
    }

    // ---------------- B cache (DRAM latency overlaps stragglers) -------------
    uint64_t b2[2][8][2];
#pragma unroll
    for (int ch = 0; ch < 2; ch++) {
        const int c = ch ? c1 : c0;
#pragma unroll
        for (int j = 0; j < RANK; j++) {
            float4 v = B4[j * N4 + c];
            v.x *= LORA_SCALE; v.y *= LORA_SCALE; v.z *= LORA_SCALE; v.w *= LORA_SCALE;
            b2[ch][j][0] = pack2(v.x, v.y);
            b2[ch][j][1] = pack2(v.z, v.w);
        }
    }

    __syncthreads();

    // ---------------- Cross-warp reduce into s_t ------------------------------
    for (int i = tid; i < nr * RANK; i += THREADS) {
        const int row = i >> 3, j = i & 7;
        float s = 0.0f;
#pragma unroll
        for (int w = 0; w < NWARPS; w++)
            s += s_part[row * (NWARPS * 8) + w * 8 + j];
        s_t[i] = s;
    }
    __syncthreads();

    // ---------------- Phase 2: out = t @ (B*scale), 2 rows/iter ---------------
    for (int rb = 0; rb < nr; rb += 2) {
        const int rA2 = rb;
        const int rB2 = (rb + 1 < nr) ? rb + 1 : rb;   // clamp (dup store harmless)

        float4 tA0 = *reinterpret_cast<const float4*>(&s_t[rA2 * RANK]);
        float4 tA1 = *reinterpret_cast<const float4*>(&s_t[rA2 * RANK + 4]);
        float4 tB0 = *reinterpret_cast<const float4*>(&s_t[rB2 * RANK]);
        float4 tB1 = *reinterpret_cast<const float4*>(&s_t[rB2 * RANK + 4]);

        uint64_t tsA[8], tsB[8];
        tsA[0] = pack2(tA0.x, tA0.x); tsA[1] = pack2(tA0.y, tA0.y);
        tsA[2] = pack2(tA0.z, tA0.z); tsA[3] = pack2(tA0.w, tA0.w);
        tsA[4] = pack2(tA1.x, tA1.x); tsA[5] = pack2(tA1.y, tA1.y);
        tsA[6] = pack2(tA1.z, tA1.z); tsA[7] = pack2(tA1.w, tA1.w);
        tsB[0] = pack2(tB0.x, tB0.x); tsB[1] = pack2(tB0.y, tB0.y);
        tsB[2] = pack2(tB0.z, tB0.z); tsB[3] = pack2(tB0.w, tB0.w);
        tsB[4] = pack2(tB1.x, tB1.x); tsB[5] = pack2(tB1.y, tB1.y);
        tsB[6] = pack2(tB1.z, tB1.z); tsB[7] = pack2(tB1.w, tB1.w);

        const size_t obA = (size_t)(r0 + rA2) * N4;
        const size_t obB = (size_t)(r0 + rB2) * N4;
#pragma unroll
        for (int ch = 0; ch < 2; ch++) {
            const int c = ch ? c1 : c0;
            uint64_t oA0 = 0, oA1 = 0, oB0 = 0, oB1 = 0;
#pragma unroll
            for (int j = 0; j < RANK; j++) {
                oA0 = fma2(tsA[j], b2[ch][j][0], oA0);
                oA1 = fma2(tsA[j], b2[ch][j][1], oA1);
                oB0 = fma2(tsB[j], b2[ch][j][0], oB0);
                oB1 = fma2(tsB[j], b2[ch][j][1], oB1);
            }
            float4 oA, oB;
            unpack2(oA0, oA.x, oA.y); unpack2(oA1, oA.z, oA.w);
            unpack2(oB0, oB.x, oB.y); unpack2(oB1, oB.z, oB.w);
            out4[obA + c] = oA;
            out4[obB + c] = oB;
        }
    }
}

extern "C" void kernel_launch(void* const* d_in, const int* in_sizes, int n_in,
                              void* d_out, int out_size)
{
    const float4* x4 = (const float4*)d_in[0];   // [4,2048,4096]
    const float4* A4 = (const float4*)d_in[1];   // [4096,8]
    const float4* B4 = (const float4*)d_in[2];   // [8,4096]
    float4* out4 = (float4*)d_out;

    const int K    = in_sizes[1] / RANK;         // 4096
    const int rows = in_sizes[0] / K;            // 8192

    int sms = 148;
    cudaDeviceGetAttribute(&sms, cudaDevAttrMultiProcessorCount, 0);

    const int smem = PSLOTS * 2048 * 16 +                        // x ring:   131072
                     MAXROWS * NWARPS * 8 * (int)sizeof(float) + // partials:  32768
                     MAXROWS * RANK * (int)sizeof(float) +       // t:          2048
                     PSLOTS * 2 * 8;                             // mbarriers:    64
    cudaFuncSetAttribute(lora_fused_kernel,
                         cudaFuncAttributeMaxDynamicSharedMemorySize, smem);

    lora_fused_kernel<<<sms, THREADS, smem>>>(x4, A4, B4, out4, rows, sms);
}